// round 1
// baseline (speedup 1.0000x reference)
#include <cuda_runtime.h>
#include <math.h>

// Problem constants (fixed by setup_inputs)
#define NB      16
#define CDIM    256
#define HID     64
#define HDIM    128
#define WDIM    128
#define NTOK    (HDIM*WDIM)     // 16384 tokens per batch
#define NPAT    256             // 16x16 patches
#define NKEEP   179             // max(10, int(256*0.7))
#define NKH     12              // ceil(179/16)
#define NKW     16
#define NPOUT   (NKH*NKW)       // 192
#define OUT_TOK (NKH*8*NKW*8)   // 12288 output tokens per batch
#define C4      (CDIM/4)        // 64 float4 per token

// Scorer tiling
#define TOK_PER_BLK 256
#define CK 32
#define NCHUNK (CDIM/CK)

// ---- device scratch (no allocations allowed) ----
// per-(batch, rowpair, iw) partial patch sums: 16 * 64 * 16
__device__ float g_part[NB * 64 * 16];
__device__ int   g_kept[NB * NPOUT];

// ---- packed fp32x2 helpers (Blackwell FFMA2) ----
__device__ __forceinline__ void ffma2(unsigned long long& d,
                                      unsigned long long a,
                                      unsigned long long b) {
    asm("fma.rn.f32x2 %0, %1, %2, %0;" : "+l"(d) : "l"(a), "l"(b));
}
__device__ __forceinline__ unsigned long long pack2(float v) {
    unsigned long long r;
    asm("mov.b64 %0, {%1, %1};" : "=l"(r) : "f"(v));
    return r;
}

// =====================================================================
// Scorer: one block = 256 consecutive tokens (= 2 image rows of one batch).
// Computes sigmoid(relu(x@W1+b1)@W2+b2) per token, reduces 2x8-token groups
// into 16 patch partial sums, writes them to g_part deterministically.
// =====================================================================
extern __shared__ float smem_raw[];

__global__ __launch_bounds__(256) void scorer_kernel(
    const float* __restrict__ tokens,
    const float* __restrict__ W1,
    const float* __restrict__ b1,
    const float* __restrict__ W2,
    const float* __restrict__ b2)
{
    float* sW = smem_raw;              // [CDIM][HID] = 16384 floats (64 KB)
    float* sx = smem_raw + CDIM * HID; // [CK][256]   =  8192 floats (32 KB)
    float* sPart = sx;                 // epilogue alias: [8][256]
    float* sTok  = sx + 8 * 256;       // epilogue alias: [256]

    const int tid = threadIdx.x;
    const int g0  = blockIdx.x * TOK_PER_BLK;     // global token index base
    const int b   = g0 / NTOK;
    const int n0  = g0 % NTOK;                    // token offset in batch
    const int rp  = n0 >> 8;                      // row-pair index 0..63

    // Load W1 into smem (float4 vectorized)
    {
        const float4* src = (const float4*)W1;
        float4* dst = (float4*)sW;
        #pragma unroll
        for (int i = tid; i < CDIM * HID / 4; i += 256) dst[i] = src[i];
    }

    unsigned long long acc[4][8];
    #pragma unroll
    for (int j = 0; j < 4; j++)
        #pragma unroll
        for (int k = 0; k < 8; k++) acc[j][k] = 0ull;

    const int l  = tid & 31;   // token-pair lane: pairs {l, l+32, l+64, l+96}
    const int hg = tid >> 5;   // hidden group: hidden hg*8 .. hg*8+7

    const float* tokBase = tokens + (size_t)g0 * CDIM;

    for (int ch = 0; ch < NCHUNK; ++ch) {
        __syncthreads();
        // stage 32 channels of this block's 256 tokens, transposed
        {
            const float4* trow =
                (const float4*)(tokBase + (size_t)tid * CDIM + ch * CK);
            #pragma unroll
            for (int i = 0; i < CK / 4; i++) {
                float4 v = trow[i];
                sx[(4 * i + 0) * 256 + tid] = v.x;
                sx[(4 * i + 1) * 256 + tid] = v.y;
                sx[(4 * i + 2) * 256 + tid] = v.z;
                sx[(4 * i + 3) * 256 + tid] = v.w;
            }
        }
        __syncthreads();

        #pragma unroll 4
        for (int cc = 0; cc < CK; ++cc) {
            const float* wrow = sW + (ch * CK + cc) * HID + hg * 8;
            float4 wa = *(const float4*)wrow;
            float4 wb = *(const float4*)(wrow + 4);
            unsigned long long w2p[8];
            w2p[0] = pack2(wa.x); w2p[1] = pack2(wa.y);
            w2p[2] = pack2(wa.z); w2p[3] = pack2(wa.w);
            w2p[4] = pack2(wb.x); w2p[5] = pack2(wb.y);
            w2p[6] = pack2(wb.z); w2p[7] = pack2(wb.w);
            const float* xr = sx + cc * 256;
            #pragma unroll
            for (int j = 0; j < 4; j++) {
                unsigned long long x2 =
                    *(const unsigned long long*)(xr + 2 * (l + 32 * j));
                #pragma unroll
                for (int k = 0; k < 8; k++) ffma2(acc[j][k], x2, w2p[k]);
            }
        }
    }
    __syncthreads();

    // Epilogue: relu + dot with W2 (thread's 8 hidden) -> partial per token
    float w2v[8], b1v[8];
    #pragma unroll
    for (int k = 0; k < 8; k++) {
        w2v[k] = W2[hg * 8 + k];
        b1v[k] = b1[hg * 8 + k];
    }
    #pragma unroll
    for (int j = 0; j < 4; j++) {
        float p0 = 0.f, p1 = 0.f;
        #pragma unroll
        for (int k = 0; k < 8; k++) {
            unsigned long long a = acc[j][k];
            float lo = __uint_as_float((unsigned)a);
            float hi = __uint_as_float((unsigned)(a >> 32));
            lo = fmaxf(lo + b1v[k], 0.f);
            hi = fmaxf(hi + b1v[k], 0.f);
            p0 += lo * w2v[k];
            p1 += hi * w2v[k];
        }
        int t0 = 2 * (l + 32 * j);
        *(float2*)(sPart + hg * 256 + t0) = make_float2(p0, p1);
    }
    __syncthreads();

    // Per-token: sum 8 hidden-group partials, sigmoid
    {
        float s = b2[0];
        #pragma unroll
        for (int h = 0; h < 8; h++) s += sPart[h * 256 + tid];
        sTok[tid] = 1.f / (1.f + expf(-s));
    }
    __syncthreads();

    // 16 patch-column partial sums for this row pair (2 rows x 8 cols)
    if (tid < 16) {
        float sum = 0.f;
        #pragma unroll
        for (int rr = 0; rr < 2; ++rr)
            #pragma unroll
            for (int cw = 0; cw < 8; ++cw)
                sum += sTok[rr * WDIM + tid * 8 + cw];
        g_part[(b * 64 + rp) * 16 + tid] = sum;   // deterministic, no atomics
    }
}

// =====================================================================
// Selection: per batch, rank patches (score desc, index asc — jax top_k
// tie semantics), keep top NKEEP, emit kept indices in ascending order,
// pad slots [NKEEP, NPOUT) with -1.
// =====================================================================
__global__ __launch_bounds__(256) void select_kernel() {
    __shared__ float s[NPAT];
    __shared__ int flag[NPAT];
    const int tid = threadIdx.x;
    for (int b = 0; b < NB; b++) {
        const int ih = tid >> 4, iw = tid & 15;
        float sc = 0.f;
        #pragma unroll
        for (int j = 0; j < 4; j++)
            sc += g_part[(b * 64 + ih * 4 + j) * 16 + iw];
        s[tid] = sc;
        __syncthreads();
        float my = s[tid];
        int rank = 0;
        for (int q = 0; q < NPAT; q++) {
            float v = s[q];
            rank += (v > my) || (v == my && q < tid);
        }
        int kept = (rank < NKEEP) ? 1 : 0;
        flag[tid] = kept;
        __syncthreads();
        if (kept) {
            int pos = 0;
            for (int q = 0; q < tid; q++) pos += flag[q];
            g_kept[b * NPOUT + pos] = tid;
        }
        if (tid >= NKEEP && tid < NPOUT) g_kept[b * NPOUT + tid] = -1;
        __syncthreads();
    }
}

// =====================================================================
// Gather: one block per output patch slot (b, kp). Copies the kept source
// patch (64 tokens x 256 floats) or zero-fills padding patches.
// =====================================================================
__global__ __launch_bounds__(256) void gather_kernel(
    const float4* __restrict__ tokens, float4* __restrict__ out)
{
    const int bk = blockIdx.x;
    const int b  = bk / NPOUT;
    const int kp = bk % NPOUT;
    const int s  = g_kept[b * NPOUT + kp];
    const int kh = kp >> 4, kw = kp & 15;

    const float4* srcB = tokens + (size_t)b * (NTOK * C4);
    float4* dstB = out + (size_t)b * (OUT_TOK * C4);

    int sih = 0, siw = 0;
    if (s >= 0) { sih = s >> 4; siw = s & 15; }
    const float4 zero = make_float4(0.f, 0.f, 0.f, 0.f);

    #pragma unroll
    for (int i = 0; i < 16; i++) {
        int idx = i * 256 + threadIdx.x;   // 0..4095 float4 of this patch
        int tp  = idx >> 6;                // token within patch 0..63
        int c4  = idx & 63;
        int ph = tp >> 3, pw = tp & 7;
        int dstTok = (kh * 8 + ph) * WDIM + kw * 8 + pw;
        float4 v = zero;
        if (s >= 0) {
            int srcTok = (sih * 8 + ph) * WDIM + siw * 8 + pw;
            v = srcB[srcTok * C4 + c4];
        }
        dstB[dstTok * C4 + c4] = v;
    }
}

// =====================================================================
extern "C" void kernel_launch(void* const* d_in, const int* in_sizes, int n_in,
                              void* d_out, int out_size)
{
    const float* tokens = (const float*)d_in[0];
    const float* W1 = (const float*)d_in[1];
    const float* b1 = (const float*)d_in[2];
    const float* W2 = (const float*)d_in[3];
    const float* b2 = (const float*)d_in[4];
    float* out = (float*)d_out;

    const int smem_bytes = (CDIM * HID + CK * 256) * (int)sizeof(float); // 96 KB
    cudaFuncSetAttribute(scorer_kernel,
                         cudaFuncAttributeMaxDynamicSharedMemorySize, smem_bytes);

    const int nblocks = (NB * NTOK) / TOK_PER_BLK;   // 1024
    scorer_kernel<<<nblocks, 256, smem_bytes>>>(tokens, W1, b1, W2, b2);
    select_kernel<<<1, 256>>>();
    gather_kernel<<<NB * NPOUT, 256>>>((const float4*)tokens, (float4*)out);
}

// round 2
// speedup vs baseline: 1.2827x; 1.2827x over previous
#include <cuda_runtime.h>
#include <math.h>

// Problem constants (fixed by setup_inputs)
#define NB      16
#define CDIM    256
#define HID     64
#define HDIM    128
#define WDIM    128
#define NTOK    (HDIM*WDIM)     // 16384 tokens per batch
#define NPAT    256             // 16x16 patches
#define NKEEP   179             // max(10, int(256*0.7))
#define NKH     12              // ceil(179/16)
#define NKW     16
#define NPOUT   (NKH*NKW)       // 192
#define OUT_TOK (NKH*8*NKW*8)   // 12288 output tokens per batch
#define C4      (CDIM/4)        // 64 float4 per token

// Scorer tiling
#define TOK_PER_BLK 256
#define CK 16
#define NCHUNK (CDIM/CK)        // 16

typedef unsigned long long ull;

// ---- device scratch (no allocations allowed) ----
__device__ float g_part[NB * 64 * 16];
__device__ int   g_kept[NB * NPOUT];

// ---- packed fp32x2 helpers (Blackwell FFMA2) ----
__device__ __forceinline__ void ffma2(ull& d, ull a, ull b) {
    asm("fma.rn.f32x2 %0, %1, %2, %0;" : "+l"(d) : "l"(a), "l"(b));
}
__device__ __forceinline__ ull pack2(float v) {
    ull r;
    asm("mov.b64 %0, {%1, %1};" : "=l"(r) : "f"(v));
    return r;
}

// =====================================================================
// Scorer: one block = 256 consecutive tokens (= 2 image rows of one batch).
// Double-buffered channel staging (1 barrier per 16-channel chunk, global
// prefetch issued in the barrier shadow). Inner product layout: 8 tokens x
// 4 hidden-PAIRS per thread; W1 rows are hidden-contiguous so weight pairs
// load pre-packed (LDS.128, no MOVs) — only x needs pack2.
// =====================================================================
extern __shared__ float smem_raw[];

__global__ __launch_bounds__(256) void scorer_kernel(
    const float* __restrict__ tokens,
    const float* __restrict__ W1,
    const float* __restrict__ b1,
    const float* __restrict__ W2,
    const float* __restrict__ b2)
{
    float* sW = smem_raw;               // [CDIM][HID] = 16384 floats (64 KB)
    float* sx = smem_raw + CDIM * HID;  // 2 x [CK][256] = 8192 floats (32 KB)
    float* sPart = sx;                  // epilogue alias: [8][256] (buf0 region)
    float* sTok  = sx + 8 * 256;        // epilogue alias: [256]

    const int tid = threadIdx.x;
    const int g0  = blockIdx.x * TOK_PER_BLK;
    const int b   = g0 / NTOK;
    const int rp  = (g0 % NTOK) >> 8;   // row-pair index 0..63

    // Load W1 into smem (float4 vectorized)
    {
        const float4* src = (const float4*)W1;
        float4* dst = (float4*)sW;
        #pragma unroll
        for (int i = tid; i < CDIM * HID / 4; i += 256) dst[i] = src[i];
    }

    ull acc[8][4];
    #pragma unroll
    for (int j = 0; j < 8; j++)
        #pragma unroll
        for (int k = 0; k < 4; k++) acc[j][k] = 0ull;

    const int l  = tid & 31;   // lane: owns tokens {4l..4l+3, 128+4l..128+4l+3}
    const int hg = tid >> 5;   // hidden group: hidden hg*8 .. hg*8+7

    const float* myRow = tokens + (size_t)(g0 + tid) * CDIM;

    // Prefetch chunk 0 (16 channels of this thread's token)
    float4 r[4];
    #pragma unroll
    for (int i = 0; i < 4; i++) r[i] = ((const float4*)myRow)[i];

    for (int ch = 0; ch < NCHUNK; ++ch) {
        float* buf = sx + (ch & 1) * (CK * 256);
        // stage: transpose 16 channels x 256 tokens
        #pragma unroll
        for (int i = 0; i < 4; i++) {
            buf[(4 * i + 0) * 256 + tid] = r[i].x;
            buf[(4 * i + 1) * 256 + tid] = r[i].y;
            buf[(4 * i + 2) * 256 + tid] = r[i].z;
            buf[(4 * i + 3) * 256 + tid] = r[i].w;
        }
        __syncthreads();
        // prefetch next chunk's globals into the barrier/compute shadow
        if (ch + 1 < NCHUNK) {
            const float4* nxt = (const float4*)(myRow + (ch + 1) * CK);
            #pragma unroll
            for (int i = 0; i < 4; i++) r[i] = nxt[i];
        }

        const float* wbase = sW + ch * CK * HID + hg * 8;
        #pragma unroll 4
        for (int cc = 0; cc < CK; ++cc) {
            const float* xr = buf + cc * 256;
            float4 xa = *(const float4*)(xr + 4 * l);
            float4 xb = *(const float4*)(xr + 128 + 4 * l);
            ull x2[8];
            x2[0] = pack2(xa.x); x2[1] = pack2(xa.y);
            x2[2] = pack2(xa.z); x2[3] = pack2(xa.w);
            x2[4] = pack2(xb.x); x2[5] = pack2(xb.y);
            x2[6] = pack2(xb.z); x2[7] = pack2(xb.w);
            const ulonglong2* wp = (const ulonglong2*)(wbase + cc * HID);
            ulonglong2 wA = wp[0];   // hidden pairs (0,1) and (2,3)
            ulonglong2 wB = wp[1];   // hidden pairs (4,5) and (6,7)
            #pragma unroll
            for (int j = 0; j < 8; j++) {
                ffma2(acc[j][0], x2[j], wA.x);
                ffma2(acc[j][1], x2[j], wA.y);
                ffma2(acc[j][2], x2[j], wB.x);
                ffma2(acc[j][3], x2[j], wB.y);
            }
        }
    }
    __syncthreads();

    // Epilogue: relu + dot with W2 over this thread's 8 hidden (4 pairs)
    float w2v[8], b1v[8];
    #pragma unroll
    for (int k = 0; k < 8; k++) {
        w2v[k] = W2[hg * 8 + k];
        b1v[k] = b1[hg * 8 + k];
    }
    #pragma unroll
    for (int j = 0; j < 8; j++) {
        float p = 0.f;
        #pragma unroll
        for (int k = 0; k < 4; k++) {
            ull a = acc[j][k];
            float lo = __uint_as_float((unsigned)a);
            float hi = __uint_as_float((unsigned)(a >> 32));
            lo = fmaxf(lo + b1v[2 * k], 0.f);
            hi = fmaxf(hi + b1v[2 * k + 1], 0.f);
            p += lo * w2v[2 * k] + hi * w2v[2 * k + 1];
        }
        int t = (j < 4) ? (4 * l + j) : (128 + 4 * l + (j - 4));
        sPart[hg * 256 + t] = p;
    }
    __syncthreads();

    // Per-token: sum 8 hidden-group partials, sigmoid
    {
        float s = b2[0];
        #pragma unroll
        for (int h = 0; h < 8; h++) s += sPart[h * 256 + tid];
        sTok[tid] = 1.f / (1.f + expf(-s));
    }
    __syncthreads();

    // 16 patch-column partial sums for this row pair (2 rows x 8 cols)
    if (tid < 16) {
        float sum = 0.f;
        #pragma unroll
        for (int rr = 0; rr < 2; ++rr)
            #pragma unroll
            for (int cw = 0; cw < 8; ++cw)
                sum += sTok[rr * WDIM + tid * 8 + cw];
        g_part[(b * 64 + rp) * 16 + tid] = sum;   // deterministic, no atomics
    }
}

// =====================================================================
// Selection: one block per batch. Rank patches (score desc, index asc —
// jax top_k tie semantics), keep top NKEEP ascending, pad with -1.
// =====================================================================
__global__ __launch_bounds__(256) void select_kernel() {
    __shared__ float s[NPAT];
    __shared__ int flag[NPAT];
    const int b = blockIdx.x;
    const int tid = threadIdx.x;
    const int ih = tid >> 4, iw = tid & 15;
    float sc = 0.f;
    #pragma unroll
    for (int j = 0; j < 4; j++)
        sc += g_part[(b * 64 + ih * 4 + j) * 16 + iw];
    s[tid] = sc;
    __syncthreads();
    float my = s[tid];
    int rank = 0;
    #pragma unroll 8
    for (int q = 0; q < NPAT; q++) {
        float v = s[q];
        rank += (v > my) || (v == my && q < tid);
    }
    int kept = (rank < NKEEP) ? 1 : 0;
    flag[tid] = kept;
    __syncthreads();
    if (kept) {
        int pos = 0;
        for (int q = 0; q < tid; q++) pos += flag[q];
        g_kept[b * NPOUT + pos] = tid;
    }
    if (tid >= NKEEP && tid < NPOUT) g_kept[b * NPOUT + tid] = -1;
}

// =====================================================================
// Gather: one block per output patch slot (b, kp). Copies the kept source
// patch (64 tokens x 256 floats) or zero-fills padding patches.
// =====================================================================
__global__ __launch_bounds__(256) void gather_kernel(
    const float4* __restrict__ tokens, float4* __restrict__ out)
{
    const int bk = blockIdx.x;
    const int b  = bk / NPOUT;
    const int kp = bk % NPOUT;
    const int s  = g_kept[b * NPOUT + kp];
    const int kh = kp >> 4, kw = kp & 15;

    const float4* srcB = tokens + (size_t)b * (NTOK * C4);
    float4* dstB = out + (size_t)b * (OUT_TOK * C4);

    int sih = 0, siw = 0;
    if (s >= 0) { sih = s >> 4; siw = s & 15; }
    const float4 zero = make_float4(0.f, 0.f, 0.f, 0.f);

    #pragma unroll
    for (int i = 0; i < 16; i++) {
        int idx = i * 256 + threadIdx.x;   // 0..4095 float4 of this patch
        int tp  = idx >> 6;                // token within patch 0..63
        int c4  = idx & 63;
        int ph = tp >> 3, pw = tp & 7;
        int dstTok = (kh * 8 + ph) * WDIM + kw * 8 + pw;
        float4 v = zero;
        if (s >= 0) {
            int srcTok = (sih * 8 + ph) * WDIM + siw * 8 + pw;
            v = srcB[srcTok * C4 + c4];
        }
        dstB[dstTok * C4 + c4] = v;
    }
}

// =====================================================================
extern "C" void kernel_launch(void* const* d_in, const int* in_sizes, int n_in,
                              void* d_out, int out_size)
{
    const float* tokens = (const float*)d_in[0];
    const float* W1 = (const float*)d_in[1];
    const float* b1 = (const float*)d_in[2];
    const float* W2 = (const float*)d_in[3];
    const float* b2 = (const float*)d_in[4];
    float* out = (float*)d_out;

    const int smem_bytes = (CDIM * HID + 2 * CK * 256) * (int)sizeof(float); // 96 KB
    cudaFuncSetAttribute(scorer_kernel,
                         cudaFuncAttributeMaxDynamicSharedMemorySize, smem_bytes);

    const int nblocks = (NB * NTOK) / TOK_PER_BLK;   // 1024
    scorer_kernel<<<nblocks, 256, smem_bytes>>>(tokens, W1, b1, W2, b2);
    select_kernel<<<NB, 256>>>();
    gather_kernel<<<NB * NPOUT, 256>>>((const float4*)tokens, (float4*)out);
}

// round 4
// speedup vs baseline: 1.5146x; 1.1809x over previous
#include <cuda_runtime.h>
#include <cuda_bf16.h>
#include <math.h>

// ---------------- problem constants ----------------
#define NB      16
#define CDIM    256
#define HID     64
#define HDIM    128
#define WDIM    128
#define NTOK    (HDIM*WDIM)     // 16384
#define NPAT    256
#define NKEEP   179
#define NKH     12
#define NKW     16
#define NPOUT   (NKH*NKW)       // 192
#define OUT_TOK (NKH*8*NKW*8)   // 12288
#define C4      (CDIM/4)

typedef unsigned int uint;

// ---------------- scorer smem map (bytes) ----------------
// W fragment image: [split2][ks16][ns8][lane32][reg2] u32 = 65536 B
// A fragment image: [split2][128 idx][33 words] u32     = 33792 B
#define SM_W     0
#define SM_A     65536
#define A_WORDS  4224            // 128*33 per split
#define SM_TOK   99328           // 128 floats
#define SM_B1    99840           // 64 floats
#define SM_W2    100096          // 64 floats
#define SMEM_BYTES 100352

// ---------------- device scratch ----------------
__device__ uint  g_Wf[16384];                 // W1 bf16 hi/lo fragment image
__device__ float g_rowpart[NB * HDIM * 16];   // per-image-row patch partials
__device__ int   g_kept[NB * NPOUT];

// ---------------- helpers ----------------
static __device__ __forceinline__ uint cvt_bf2(float hi, float lo) {
    uint d;
    asm("cvt.rn.bf16x2.f32 %0, %1, %2;" : "=r"(d) : "f"(hi), "f"(lo));
    return d;
}
static __device__ __forceinline__ float bf_lo(uint h) { return __uint_as_float(h << 16); }
static __device__ __forceinline__ float bf_hi(uint h) { return __uint_as_float(h & 0xffff0000u); }

static __device__ __forceinline__ void mma16816(float* d, const uint* a,
                                                uint b0, uint b1) {
    asm("mma.sync.aligned.m16n8k16.row.col.f32.bf16.bf16.f32 "
        "{%0,%1,%2,%3}, {%4,%5,%6,%7}, {%8,%9}, {%0,%1,%2,%3};"
        : "+f"(d[0]), "+f"(d[1]), "+f"(d[2]), "+f"(d[3])
        : "r"(a[0]), "r"(a[1]), "r"(a[2]), "r"(a[3]), "r"(b0), "r"(b1));
}

// =====================================================================
// prep: W1 [256k x 64n] fp32 -> bf16 hi/lo in m16n8k16 B-fragment order.
// u = ((ks*8+ns)*32 + lane)*2 + reg ; k0 = ks*16 + 2t + 8*reg ; n = ns*8+g
// =====================================================================
__global__ __launch_bounds__(256) void prep_W_kernel(const float* __restrict__ W1) {
    int u = blockIdx.x * 256 + threadIdx.x;     // 0..8191
    int reg = u & 1, lane = (u >> 1) & 31, ns = (u >> 6) & 7, ks = u >> 9;
    int g = lane >> 2, t = lane & 3;
    int k0 = ks * 16 + 2 * t + 8 * reg;
    int n  = ns * 8 + g;
    float w0 = W1[k0 * HID + n];
    float w1 = W1[(k0 + 1) * HID + n];
    uint h = cvt_bf2(w1, w0);                   // low half = lower k
    uint l = cvt_bf2(w1 - bf_hi(h), w0 - bf_lo(h));
    g_Wf[u] = h;
    g_Wf[8192 + u] = l;
}

// =====================================================================
// scorer: one block = 128 tokens (1 image row). bf16 3-split HMMA GEMM
// (M=128, N=64, K=256), fused bias/relu/W2/sigmoid/patch-partial epilogue.
// =====================================================================
__global__ __launch_bounds__(128, 2) void scorer_kernel(
    const float* __restrict__ tokens,
    const float* __restrict__ b1g,
    const float* __restrict__ W2g,
    const float* __restrict__ b2g)
{
    extern __shared__ char smem[];
    uint*  sW   = (uint*)(smem + SM_W);
    uint*  sA   = (uint*)(smem + SM_A);         // hi [0,4224), lo [4224,8448)
    float* sTok = (float*)(smem + SM_TOK);
    float* sb1  = (float*)(smem + SM_B1);
    float* sw2  = (float*)(smem + SM_W2);

    const int tid  = threadIdx.x;               // 0..127
    const int w    = tid >> 5;                  // warp 0..3 -> msteps {2w,2w+1}
    const int lane = tid & 31;
    const int blk  = blockIdx.x;                // 0..2047

    // stage W fragment image + biases
    {
        const float4* s = (const float4*)g_Wf;
        float4* d4 = (float4*)sW;
        #pragma unroll
        for (int i = tid; i < 16384 / 4; i += 128) d4[i] = s[i];
    }
    if (tid < 64) { sb1[tid] = b1g[tid]; sw2[tid] = W2g[tid]; }

    float acc[2][8][4];
    #pragma unroll
    for (int a = 0; a < 2; a++)
        #pragma unroll
        for (int b = 0; b < 8; b++)
            #pragma unroll
            for (int c = 0; c < 4; c++) acc[a][b][c] = 0.f;

    // convert-thread indices: this thread owns token m = tid
    const int m = tid;
    const int mstep = m >> 4, r = m & 15, q = r & 7, rh = r >> 3;
    const float4* rowp = (const float4*)(tokens + ((size_t)blk * 128 + m) * CDIM);

    for (int c = 0; c < 4; ++c) {               // 4 chunks of 64 channels
        __syncthreads();                        // buffer free (prev mma done)
        // ---- convert 64 channels into A-fragment layout (hi+lo) ----
        #pragma unroll
        for (int jj = 0; jj < 8; ++jj) {        // 8 channels per jj
            float4 a = rowp[c * 16 + 2 * jj];
            float4 b = rowp[c * 16 + 2 * jj + 1];
            uint h0 = cvt_bf2(a.y, a.x);
            uint h1 = cvt_bf2(a.w, a.z);
            uint h2 = cvt_bf2(b.y, b.x);
            uint h3 = cvt_bf2(b.w, b.z);
            uint l0 = cvt_bf2(a.y - bf_hi(h0), a.x - bf_lo(h0));
            uint l1 = cvt_bf2(a.w - bf_hi(h1), a.z - bf_lo(h1));
            uint l2 = cvt_bf2(b.y - bf_hi(h2), b.x - bf_lo(h2));
            uint l3 = cvt_bf2(b.w - bf_hi(h3), b.z - bf_lo(h3));
            int kl = jj >> 1, kh = jj & 1;
            uint w0 = (uint)((((kl * 8 + mstep) * 4) + rh + 2 * kh) * 33 + 4 * q);
            sA[w0 + 0] = h0; sA[w0 + 1] = h1; sA[w0 + 2] = h2; sA[w0 + 3] = h3;
            sA[A_WORDS + w0 + 0] = l0; sA[A_WORDS + w0 + 1] = l1;
            sA[A_WORDS + w0 + 2] = l2; sA[A_WORDS + w0 + 3] = l3;
        }
        __syncthreads();                        // data ready

        // ---- MMA over this chunk's 4 ksteps ----
        #pragma unroll
        for (int kl = 0; kl < 4; ++kl) {
            uint Ah[2][4], Al[2][4];
            #pragma unroll
            for (int dm = 0; dm < 2; ++dm) {
                int msel = 2 * w + dm;
                #pragma unroll
                for (int rg = 0; rg < 4; ++rg) {
                    uint idx = (uint)(((kl * 8 + msel) * 4 + rg) * 33 + lane);
                    Ah[dm][rg] = sA[idx];
                    Al[dm][rg] = sA[A_WORDS + idx];
                }
            }
            int ks = c * 4 + kl;
            #pragma unroll
            for (int ns = 0; ns < 8; ++ns) {
                uint boff = (uint)(((ks * 8 + ns) * 32 + lane) * 2);
                uint2 bh = *(const uint2*)(sW + boff);
                uint2 bl = *(const uint2*)(sW + 8192 + boff);
                #pragma unroll
                for (int dm = 0; dm < 2; ++dm) {
                    mma16816(acc[dm][ns], Ah[dm], bh.x, bh.y);
                    mma16816(acc[dm][ns], Al[dm], bh.x, bh.y);
                    mma16816(acc[dm][ns], Ah[dm], bl.x, bl.y);
                }
            }
        }
    }

    // ---- epilogue: bias + relu + W2 dot, reduce over k-lanes, sigmoid ----
    const int t4 = lane & 3, g = lane >> 2;
    const float b2v = b2g[0];
    float tv[4];
    #pragma unroll
    for (int dm = 0; dm < 2; ++dm)
        #pragma unroll
        for (int rh2 = 0; rh2 < 2; ++rh2) {
            float s = 0.f;
            #pragma unroll
            for (int ns = 0; ns < 8; ++ns)
                #pragma unroll
                for (int j = 0; j < 2; ++j) {
                    int n = ns * 8 + 2 * t4 + j;
                    float h = acc[dm][ns][2 * rh2 + j] + sb1[n];
                    s += fmaxf(h, 0.f) * sw2[n];
                }
            tv[dm * 2 + rh2] = s;
        }
    #pragma unroll
    for (int k = 0; k < 4; ++k) {
        tv[k] += __shfl_xor_sync(0xffffffffu, tv[k], 1);
        tv[k] += __shfl_xor_sync(0xffffffffu, tv[k], 2);
    }
    if (t4 == 0) {
        #pragma unroll
        for (int k = 0; k < 4; ++k) {
            int dm = k >> 1, rh2 = k & 1;
            int token = (2 * w + dm) * 16 + g + 8 * rh2;
            float s = tv[k] + b2v;
            sTok[token] = 1.f / (1.f + expf(-s));
        }
    }
    __syncthreads();

    // per-row patch partials (8 tokens per patch column)
    if (tid < 16) {
        float sum = 0.f;
        #pragma unroll
        for (int cc = 0; cc < 8; ++cc) sum += sTok[tid * 8 + cc];
        int bb = blk >> 7, y = blk & 127;
        g_rowpart[(bb * HDIM + y) * 16 + tid] = sum;   // deterministic
    }
}

// =====================================================================
// selection: one block per batch; jax top_k tie semantics
// (score desc, index asc), kept indices ascending, pad with -1.
// =====================================================================
__global__ __launch_bounds__(256) void select_kernel() {
    __shared__ float s[NPAT];
    __shared__ int flag[NPAT];
    const int b = blockIdx.x;
    const int tid = threadIdx.x;
    const int ih = tid >> 4, iw = tid & 15;
    float sc = 0.f;
    #pragma unroll
    for (int r = 0; r < 8; r++)
        sc += g_rowpart[(b * HDIM + ih * 8 + r) * 16 + iw];
    s[tid] = sc;
    __syncthreads();
    float my = s[tid];
    int rank = 0;
    #pragma unroll 8
    for (int q = 0; q < NPAT; q++) {
        float v = s[q];
        rank += (v > my) || (v == my && q < tid);
    }
    int kept = (rank < NKEEP) ? 1 : 0;
    flag[tid] = kept;
    __syncthreads();
    if (kept) {
        int pos = 0;
        for (int q = 0; q < tid; q++) pos += flag[q];
        g_kept[b * NPOUT + pos] = tid;
    }
    if (tid >= NKEEP && tid < NPOUT) g_kept[b * NPOUT + tid] = -1;
}

// =====================================================================
// gather: one block per output patch slot
// =====================================================================
__global__ __launch_bounds__(256) void gather_kernel(
    const float4* __restrict__ tokens, float4* __restrict__ out)
{
    const int bk = blockIdx.x;
    const int b  = bk / NPOUT;
    const int kp = bk % NPOUT;
    const int s  = g_kept[b * NPOUT + kp];
    const int kh = kp >> 4, kw = kp & 15;

    const float4* srcB = tokens + (size_t)b * (NTOK * C4);
    float4* dstB = out + (size_t)b * (OUT_TOK * C4);

    int sih = 0, siw = 0;
    if (s >= 0) { sih = s >> 4; siw = s & 15; }
    const float4 zero = make_float4(0.f, 0.f, 0.f, 0.f);

    #pragma unroll
    for (int i = 0; i < 16; i++) {
        int idx = i * 256 + threadIdx.x;
        int tp  = idx >> 6;
        int c4  = idx & 63;
        int ph = tp >> 3, pw = tp & 7;
        int dstTok = (kh * 8 + ph) * WDIM + kw * 8 + pw;
        float4 v = zero;
        if (s >= 0) {
            int srcTok = (sih * 8 + ph) * WDIM + siw * 8 + pw;
            v = srcB[srcTok * C4 + c4];
        }
        dstB[dstTok * C4 + c4] = v;
    }
}

// =====================================================================
extern "C" void kernel_launch(void* const* d_in, const int* in_sizes, int n_in,
                              void* d_out, int out_size)
{
    const float* tokens = (const float*)d_in[0];
    const float* W1 = (const float*)d_in[1];
    const float* b1 = (const float*)d_in[2];
    const float* W2 = (const float*)d_in[3];
    const float* b2 = (const float*)d_in[4];
    float* out = (float*)d_out;

    cudaFuncSetAttribute(scorer_kernel,
                         cudaFuncAttributeMaxDynamicSharedMemorySize, SMEM_BYTES);

    prep_W_kernel<<<32, 256>>>(W1);
    scorer_kernel<<<NB * HDIM, 128, SMEM_BYTES>>>(tokens, b1, W2, b2);
    select_kernel<<<NB, 256>>>();
    gather_kernel<<<NB * NPOUT, 256>>>((const float4*)tokens, (float4*)out);
}

// round 6
// speedup vs baseline: 1.6586x; 1.0950x over previous
#include <cuda_runtime.h>
#include <cuda_bf16.h>
#include <math.h>

// ---------------- problem constants ----------------
#define NB      16
#define CDIM    256
#define HID     64
#define HDIM    128
#define WDIM    128
#define NTOK    (HDIM*WDIM)     // 16384
#define NPAT    256
#define NKEEP   179
#define NKH     12
#define NKW     16
#define NPOUT   (NKH*NKW)       // 192
#define OUT_TOK (NKH*8*NKW*8)   // 12288
#define C4      (CDIM/4)

typedef unsigned int uint;

// ---------------- scorer smem map (bytes) ----------------
// A fragment image: [split2][128 idx][33 words] u32 = 33792 B
#define SM_A     0
#define A_WORDS  4224            // 128*33 per split
#define SM_TOK   33792           // 128 floats
#define SM_B1    34304           // 64 floats
#define SM_W2    34560           // 64 floats
#define SMEM_BYTES 34816

// ---------------- device scratch ----------------
__device__ uint  g_Wf[16384];                 // W1 bf16 hi/lo fragment image
__device__ float g_rowpart[NB * HDIM * 16];   // per-image-row patch partials
__device__ int   g_kept[NB * NPOUT];

// ---------------- helpers ----------------
static __device__ __forceinline__ uint cvt_bf2(float hi, float lo) {
    uint d;
    asm("cvt.rn.bf16x2.f32 %0, %1, %2;" : "=r"(d) : "f"(hi), "f"(lo));
    return d;
}
static __device__ __forceinline__ float bf_lo(uint h) { return __uint_as_float(h << 16); }
static __device__ __forceinline__ float bf_hi(uint h) { return __uint_as_float(h & 0xffff0000u); }

static __device__ __forceinline__ void mma16816(float* d, const uint* a,
                                                uint b0, uint b1) {
    asm("mma.sync.aligned.m16n8k16.row.col.f32.bf16.bf16.f32 "
        "{%0,%1,%2,%3}, {%4,%5,%6,%7}, {%8,%9}, {%0,%1,%2,%3};"
        : "+f"(d[0]), "+f"(d[1]), "+f"(d[2]), "+f"(d[3])
        : "r"(a[0]), "r"(a[1]), "r"(a[2]), "r"(a[3]), "r"(b0), "r"(b1));
}

// =====================================================================
// prep: W1 [256k x 64n] fp32 -> bf16 hi/lo in m16n8k16 B-fragment order.
// u = ((ks*8+ns)*32 + lane)*2 + reg ; k0 = ks*16 + 2t + 8*reg ; n = ns*8+g
// =====================================================================
__global__ __launch_bounds__(256) void prep_W_kernel(const float* __restrict__ W1) {
    int u = blockIdx.x * 256 + threadIdx.x;     // 0..8191
    int reg = u & 1, lane = (u >> 1) & 31, ns = (u >> 6) & 7, ks = u >> 9;
    int g = lane >> 2, t = lane & 3;
    int k0 = ks * 16 + 2 * t + 8 * reg;
    int n  = ns * 8 + g;
    float w0 = W1[k0 * HID + n];
    float w1 = W1[(k0 + 1) * HID + n];
    uint h = cvt_bf2(w1, w0);                   // low half = lower k
    uint l = cvt_bf2(w1 - bf_hi(h), w0 - bf_lo(h));
    g_Wf[u] = h;
    g_Wf[8192 + u] = l;
}

// =====================================================================
// scorer: one block = 128 tokens (1 image row). bf16 3-split HMMA GEMM
// (M=128, N=64, K=256). B fragments stream from L1/L2-resident g_Wf;
// only A fragments staged in smem -> ~35 KB/CTA -> 4 CTAs/SM.
// =====================================================================
__global__ __launch_bounds__(128, 4) void scorer_kernel(
    const float* __restrict__ tokens,
    const float* __restrict__ b1g,
    const float* __restrict__ W2g,
    const float* __restrict__ b2g)
{
    extern __shared__ char smem[];
    uint*  sA   = (uint*)(smem + SM_A);         // hi [0,4224), lo [4224,8448)
    float* sTok = (float*)(smem + SM_TOK);
    float* sb1  = (float*)(smem + SM_B1);
    float* sw2  = (float*)(smem + SM_W2);

    const int tid  = threadIdx.x;               // 0..127
    const int w    = tid >> 5;                  // warp 0..3 -> msteps {2w,2w+1}
    const int lane = tid & 31;
    const int blk  = blockIdx.x;                // 0..2047

    if (tid < 64) { sb1[tid] = b1g[tid]; sw2[tid] = W2g[tid]; }

    float acc[2][8][4];
    #pragma unroll
    for (int a = 0; a < 2; a++)
        #pragma unroll
        for (int b = 0; b < 8; b++)
            #pragma unroll
            for (int c = 0; c < 4; c++) acc[a][b][c] = 0.f;

    // convert-thread indices: this thread owns token m = tid
    const int m = tid;
    const int mstep = m >> 4, r = m & 15, q = r & 7, rh = r >> 3;
    const float4* rowp = (const float4*)(tokens + ((size_t)blk * 128 + m) * CDIM);

    const uint2* gWh = (const uint2*)g_Wf;            // hi image as uint2
    const uint2* gWl = (const uint2*)(g_Wf + 8192);   // lo image

    for (int c = 0; c < 4; ++c) {               // 4 chunks of 64 channels
        __syncthreads();                        // buffer free (prev mma done)
        // ---- convert 64 channels into A-fragment layout (hi+lo) ----
        #pragma unroll
        for (int jj = 0; jj < 8; ++jj) {        // 8 channels per jj
            float4 a = rowp[c * 16 + 2 * jj];
            float4 b = rowp[c * 16 + 2 * jj + 1];
            uint h0 = cvt_bf2(a.y, a.x);
            uint h1 = cvt_bf2(a.w, a.z);
            uint h2 = cvt_bf2(b.y, b.x);
            uint h3 = cvt_bf2(b.w, b.z);
            uint l0 = cvt_bf2(a.y - bf_hi(h0), a.x - bf_lo(h0));
            uint l1 = cvt_bf2(a.w - bf_hi(h1), a.z - bf_lo(h1));
            uint l2 = cvt_bf2(b.y - bf_hi(h2), b.x - bf_lo(h2));
            uint l3 = cvt_bf2(b.w - bf_hi(h3), b.z - bf_lo(h3));
            int kl = jj >> 1, kh = jj & 1;
            uint w0 = (uint)((((kl * 8 + mstep) * 4) + rh + 2 * kh) * 33 + 4 * q);
            sA[w0 + 0] = h0; sA[w0 + 1] = h1; sA[w0 + 2] = h2; sA[w0 + 3] = h3;
            sA[A_WORDS + w0 + 0] = l0; sA[A_WORDS + w0 + 1] = l1;
            sA[A_WORDS + w0 + 2] = l2; sA[A_WORDS + w0 + 3] = l3;
        }
        __syncthreads();                        // data ready

        // ---- MMA over this chunk's 4 ksteps ----
        #pragma unroll
        for (int kl = 0; kl < 4; ++kl) {
            uint Ah[2][4], Al[2][4];
            #pragma unroll
            for (int dm = 0; dm < 2; ++dm) {
                int msel = 2 * w + dm;
                #pragma unroll
                for (int rg = 0; rg < 4; ++rg) {
                    uint idx = (uint)(((kl * 8 + msel) * 4 + rg) * 33 + lane);
                    Ah[dm][rg] = sA[idx];
                    Al[dm][rg] = sA[A_WORDS + idx];
                }
            }
            int ks = c * 4 + kl;
            #pragma unroll
            for (int ns = 0; ns < 8; ++ns) {
                uint bi = (uint)((ks * 8 + ns) * 32 + lane);
                uint2 bh = __ldg(&gWh[bi]);
                uint2 bl = __ldg(&gWl[bi]);
                #pragma unroll
                for (int dm = 0; dm < 2; ++dm) {
                    mma16816(acc[dm][ns], Ah[dm], bh.x, bh.y);
                    mma16816(acc[dm][ns], Al[dm], bh.x, bh.y);
                    mma16816(acc[dm][ns], Ah[dm], bl.x, bl.y);
                }
            }
        }
    }

    // ---- epilogue: bias + relu + W2 dot, reduce over k-lanes, sigmoid ----
    const int t4 = lane & 3, g = lane >> 2;
    const float b2v = b2g[0];
    float tv[4];
    #pragma unroll
    for (int dm = 0; dm < 2; ++dm)
        #pragma unroll
        for (int rh2 = 0; rh2 < 2; ++rh2) {
            float s = 0.f;
            #pragma unroll
            for (int ns = 0; ns < 8; ++ns)
                #pragma unroll
                for (int j = 0; j < 2; ++j) {
                    int n = ns * 8 + 2 * t4 + j;
                    float h = acc[dm][ns][2 * rh2 + j] + sb1[n];
                    s += fmaxf(h, 0.f) * sw2[n];
                }
            tv[dm * 2 + rh2] = s;
        }
    #pragma unroll
    for (int k = 0; k < 4; ++k) {
        tv[k] += __shfl_xor_sync(0xffffffffu, tv[k], 1);
        tv[k] += __shfl_xor_sync(0xffffffffu, tv[k], 2);
    }
    if (t4 == 0) {
        #pragma unroll
        for (int k = 0; k < 4; ++k) {
            int dm = k >> 1, rh2 = k & 1;
            int token = (2 * w + dm) * 16 + g + 8 * rh2;
            float s = tv[k] + b2v;
            sTok[token] = 1.f / (1.f + expf(-s));
        }
    }
    __syncthreads();

    // per-row patch partials (8 tokens per patch column)
    if (tid < 16) {
        float sum = 0.f;
        #pragma unroll
        for (int cc = 0; cc < 8; ++cc) sum += sTok[tid * 8 + cc];
        int bb = blk >> 7, y = blk & 127;
        g_rowpart[(bb * HDIM + y) * 16 + tid] = sum;   // deterministic
    }
}

// =====================================================================
// selection: one block per batch; jax top_k tie semantics
// (score desc, index asc), kept indices ascending, pad with -1.
// =====================================================================
__global__ __launch_bounds__(256) void select_kernel() {
    __shared__ float s[NPAT];
    __shared__ int flag[NPAT];
    const int b = blockIdx.x;
    const int tid = threadIdx.x;
    const int ih = tid >> 4, iw = tid & 15;
    float sc = 0.f;
    #pragma unroll
    for (int r = 0; r < 8; r++)
        sc += g_rowpart[(b * HDIM + ih * 8 + r) * 16 + iw];
    s[tid] = sc;
    __syncthreads();
    float my = s[tid];
    int rank = 0;
    #pragma unroll 8
    for (int q = 0; q < NPAT; q++) {
        float v = s[q];
        rank += (v > my) || (v == my && q < tid);
    }
    int kept = (rank < NKEEP) ? 1 : 0;
    flag[tid] = kept;
    __syncthreads();
    if (kept) {
        int pos = 0;
        for (int q = 0; q < tid; q++) pos += flag[q];
        g_kept[b * NPOUT + pos] = tid;
    }
    if (tid >= NKEEP && tid < NPOUT) g_kept[b * NPOUT + tid] = -1;
}

// =====================================================================
// gather: one block per output patch slot
// =====================================================================
__global__ __launch_bounds__(256) void gather_kernel(
    const float4* __restrict__ tokens, float4* __restrict__ out)
{
    const int bk = blockIdx.x;
    const int b  = bk / NPOUT;
    const int kp = bk % NPOUT;
    const int s  = g_kept[b * NPOUT + kp];
    const int kh = kp >> 4, kw = kp & 15;

    const float4* srcB = tokens + (size_t)b * (NTOK * C4);
    float4* dstB = out + (size_t)b * (OUT_TOK * C4);

    int sih = 0, siw = 0;
    if (s >= 0) { sih = s >> 4; siw = s & 15; }
    const float4 zero = make_float4(0.f, 0.f, 0.f, 0.f);

    #pragma unroll
    for (int i = 0; i < 16; i++) {
        int idx = i * 256 + threadIdx.x;
        int tp  = idx >> 6;
        int c4  = idx & 63;
        int ph = tp >> 3, pw = tp & 7;
        int dstTok = (kh * 8 + ph) * WDIM + kw * 8 + pw;
        float4 v = zero;
        if (s >= 0) {
            int srcTok = (sih * 8 + ph) * WDIM + siw * 8 + pw;
            v = srcB[srcTok * C4 + c4];
        }
        dstB[dstTok * C4 + c4] = v;
    }
}

// =====================================================================
extern "C" void kernel_launch(void* const* d_in, const int* in_sizes, int n_in,
                              void* d_out, int out_size)
{
    const float* tokens = (const float*)d_in[0];
    const float* W1 = (const float*)d_in[1];
    const float* b1 = (const float*)d_in[2];
    const float* W2 = (const float*)d_in[3];
    const float* b2 = (const float*)d_in[4];
    float* out = (float*)d_out;

    cudaFuncSetAttribute(scorer_kernel,
                         cudaFuncAttributeMaxDynamicSharedMemorySize, SMEM_BYTES);

    prep_W_kernel<<<32, 256>>>(W1);
    scorer_kernel<<<NB * HDIM, 128, SMEM_BYTES>>>(tokens, b1, W2, b2);
    select_kernel<<<NB, 256>>>();
    gather_kernel<<<NB * NPOUT, 256>>>((const float4*)tokens, (float4*)out);
}